// round 2
// baseline (speedup 1.0000x reference)
#include <cuda_runtime.h>
#include <math.h>

// Problem constants
#define N_NODES 10000
#define N_EDGES 160000
#define H       512
#define HH      (H * H)          // 262144
#define NREL    2
#define NB      30
#define KTOT    (3 * H)          // 1536: [w0 rows | w1 rows | root rows]

// ---------------- scratch (static device globals; no allocations) ----------
__device__ float d_wcat1[KTOT * H];                       // 3 MB
__device__ float d_wcat2[KTOT * H];                       // 3 MB
__device__ float d_ybuf[(size_t)NREL * N_NODES * H];      // 40 MB
__device__ float d_hbuf[(size_t)N_NODES * H];             // 20 MB
__device__ float d_gate[N_NODES * NREL];                  // 80 KB

// ---------------------------------------------------------------------------
// w[r] = sum_b att[r,b] * basis[b]  and copy root into rows [1024,1536)
__global__ void k_wcat(const float* __restrict__ basis,
                       const float* __restrict__ att,
                       const float* __restrict__ root,
                       float* __restrict__ wcat) {
    __shared__ float s_att[2 * NB];
    if (threadIdx.x < 2 * NB) s_att[threadIdx.x] = att[threadIdx.x];
    __syncthreads();
    int idx = blockIdx.x * blockDim.x + threadIdx.x;
    if (idx >= HH) return;
    float a0 = 0.f, a1 = 0.f;
#pragma unroll
    for (int b = 0; b < NB; b++) {
        float bv = __ldg(&basis[(size_t)b * HH + idx]);
        a0 += s_att[b] * bv;
        a1 += s_att[NB + b] * bv;
    }
    wcat[idx]          = a0;
    wcat[HH + idx]     = a1;
    wcat[2 * HH + idx] = root[idx];
}

// ---------------------------------------------------------------------------
// g[n][r] = sigmoid( x[n] . gate_w[r] )   — one warp per node, both relations
__global__ void k_gates(const float* __restrict__ x,
                        const float* __restrict__ gw,
                        float* __restrict__ g) {
    int warp = (blockIdx.x * blockDim.x + threadIdx.x) >> 5;
    int lane = threadIdx.x & 31;
    if (warp >= N_NODES) return;
    const float4* xr = (const float4*)(x + (size_t)warp * H);
    const float4* g0 = (const float4*)gw;
    const float4* g1 = (const float4*)(gw + H);
    float s0 = 0.f, s1 = 0.f;
#pragma unroll
    for (int k = lane; k < H / 4; k += 32) {
        float4 v = __ldg(xr + k);
        float4 a = __ldg(g0 + k);
        float4 b = __ldg(g1 + k);
        s0 += v.x * a.x + v.y * a.y + v.z * a.z + v.w * a.w;
        s1 += v.x * b.x + v.y * b.y + v.z * b.z + v.w * b.w;
    }
#pragma unroll
    for (int o = 16; o > 0; o >>= 1) {
        s0 += __shfl_xor_sync(0xFFFFFFFFu, s0, o);
        s1 += __shfl_xor_sync(0xFFFFFFFFu, s1, o);
    }
    if (lane == 0) {
        g[warp * 2 + 0] = 1.f / (1.f + __expf(-s0));
        g[warp * 2 + 1] = 1.f / (1.f + __expf(-s1));
    }
}

// ---------------------------------------------------------------------------
__global__ void k_zero(float4* __restrict__ p, int n4) {
    int i = blockIdx.x * blockDim.x + threadIdx.x;
    if (i < n4) p[i] = make_float4(0.f, 0.f, 0.f, 0.f);
}

// ---------------------------------------------------------------------------
// Edge scatter: y[r_e][row_e] += gate_e * x[col_e]    (one warp per edge)
// Vector L2 reductions (red.global.add.v4.f32) — 4x fewer atomic ops.
__global__ void k_scatter(const float* __restrict__ x,
                          const int* __restrict__ eidx,
                          const int* __restrict__ etype,
                          const float* __restrict__ g,
                          float* __restrict__ y) {
    int e    = (blockIdx.x * blockDim.x + threadIdx.x) >> 5;
    int lane = threadIdx.x & 31;
    if (e >= N_EDGES) return;
    int row = eidx[e];
    int col = eidx[N_EDGES + e];
    int r   = etype[e];
    float gv = g[col * 2 + r];
    const float4* xs = (const float4*)(x + (size_t)col * H);
    float* yd = y + ((size_t)r * N_NODES + row) * H;
#pragma unroll
    for (int k = lane; k < H / 4; k += 32) {
        float4 v = __ldg(xs + k);
        asm volatile("red.global.add.v4.f32 [%0], {%1, %2, %3, %4};"
                     :: "l"(yd + 4 * k),
                        "f"(gv * v.x), "f"(gv * v.y), "f"(gv * v.z), "f"(gv * v.w)
                     : "memory");
    }
}

// ---------------------------------------------------------------------------
// Fused GEMM: out[n] = [y0[n] | y1[n] | xin[n]] (1x1536) @ wcat (1536x512) + bias
// BM=128, BN=64, BK=16, 256 threads, 8x4 microtile, double-buffered smem.
#define BM 128
#define BN 64
#define BK 16
#define NT (KTOT / BK)   // 96 K-steps

__global__ __launch_bounds__(256, 2) void k_gemm(const float* __restrict__ y,
                                                 const float* __restrict__ xin,
                                                 const float* __restrict__ w,
                                                 const float* __restrict__ bias,
                                                 float* __restrict__ out,
                                                 int do_relu) {
    __shared__ float As[2][BK][BM];
    __shared__ float Bs[2][BK][BN];
    int t  = threadIdx.x;
    int m0 = blockIdx.y * BM;
    int n0 = blockIdx.x * BN;
    int ty = t >> 4;          // 0..15 -> output rows ty*8 .. +7
    int tx = t & 15;          // 0..15 -> output cols tx*4 .. +3

    float acc[8][4];
#pragma unroll
    for (int i = 0; i < 8; i++)
#pragma unroll
        for (int j = 0; j < 4; j++) acc[i][j] = 0.f;

    // A tile load: thread loads 8 consecutive k-floats at row t/2, k off (t&1)*8
    int la_m = t >> 1;
    int la_k = (t & 1) * 8;
    // B tile load: thread loads float4 at k=t/16, n=(t%16)*4
    int lb_k = t >> 4;
    int lb_n = (t & 15) * 4;

    int gm_ok = (m0 + la_m) < N_NODES;

    // ---- prologue: load tile 0 into buffer 0 ----
    float4 a0, a1, bv;
    {
        if (gm_ok) {
            const float* src = y + (size_t)(m0 + la_m) * H + la_k;
            a0 = *(const float4*)(src);
            a1 = *(const float4*)(src + 4);
        } else {
            a0 = make_float4(0.f, 0.f, 0.f, 0.f);
            a1 = a0;
        }
        bv = *(const float4*)(w + (size_t)lb_k * H + n0 + lb_n);
        As[0][la_k + 0][la_m] = a0.x;
        As[0][la_k + 1][la_m] = a0.y;
        As[0][la_k + 2][la_m] = a0.z;
        As[0][la_k + 3][la_m] = a0.w;
        As[0][la_k + 4][la_m] = a1.x;
        As[0][la_k + 5][la_m] = a1.y;
        As[0][la_k + 6][la_m] = a1.z;
        As[0][la_k + 7][la_m] = a1.w;
        *(float4*)&Bs[0][lb_k][lb_n] = bv;
    }
    __syncthreads();

    int cur = 0;
    for (int it = 0; it < NT; it++) {
        int has_next = (it + 1) < NT;
        // ---- prefetch next tile into registers ----
        if (has_next) {
            int kk = (it + 1) * BK;
            int reg  = kk >> 9;           // which 512-row region of virtual A
            int kloc = kk & 511;
            const float* abase;
            if (reg == 0)      abase = y;
            else if (reg == 1) abase = y + (size_t)N_NODES * H;
            else               abase = xin;
            if (gm_ok) {
                const float* src = abase + (size_t)(m0 + la_m) * H + kloc + la_k;
                a0 = *(const float4*)(src);
                a1 = *(const float4*)(src + 4);
            } else {
                a0 = make_float4(0.f, 0.f, 0.f, 0.f);
                a1 = a0;
            }
            bv = *(const float4*)(w + (size_t)(kk + lb_k) * H + n0 + lb_n);
        }

        // ---- compute on current buffer ----
#pragma unroll
        for (int k = 0; k < BK; k++) {
            float4 b4  = *(const float4*)&Bs[cur][k][tx * 4];
            float4 av0 = *(const float4*)&As[cur][k][ty * 8];
            float4 av1 = *(const float4*)&As[cur][k][ty * 8 + 4];
            float a[8] = {av0.x, av0.y, av0.z, av0.w, av1.x, av1.y, av1.z, av1.w};
#pragma unroll
            for (int i = 0; i < 8; i++) {
                acc[i][0] += a[i] * b4.x;
                acc[i][1] += a[i] * b4.y;
                acc[i][2] += a[i] * b4.z;
                acc[i][3] += a[i] * b4.w;
            }
        }

        // ---- store prefetched tile into the other buffer ----
        if (has_next) {
            int nxt = cur ^ 1;
            As[nxt][la_k + 0][la_m] = a0.x;
            As[nxt][la_k + 1][la_m] = a0.y;
            As[nxt][la_k + 2][la_m] = a0.z;
            As[nxt][la_k + 3][la_m] = a0.w;
            As[nxt][la_k + 4][la_m] = a1.x;
            As[nxt][la_k + 5][la_m] = a1.y;
            As[nxt][la_k + 6][la_m] = a1.z;
            As[nxt][la_k + 7][la_m] = a1.w;
            *(float4*)&Bs[nxt][lb_k][lb_n] = bv;
            __syncthreads();
            cur = nxt;
        }
    }

    float4 bb = *(const float4*)(bias + n0 + tx * 4);
#pragma unroll
    for (int i = 0; i < 8; i++) {
        int gm = m0 + ty * 8 + i;
        if (gm < N_NODES) {
            float4 v;
            v.x = acc[i][0] + bb.x;
            v.y = acc[i][1] + bb.y;
            v.z = acc[i][2] + bb.z;
            v.w = acc[i][3] + bb.w;
            if (do_relu) {
                v.x = fmaxf(v.x, 0.f);
                v.y = fmaxf(v.y, 0.f);
                v.z = fmaxf(v.z, 0.f);
                v.w = fmaxf(v.w, 0.f);
            }
            *(float4*)(out + (size_t)gm * H + n0 + tx * 4) = v;
        }
    }
}

// ---------------------------------------------------------------------------
extern "C" void kernel_launch(void* const* d_in, const int* in_sizes, int n_in,
                              void* d_out, int out_size) {
    const float* x      = (const float*)d_in[0];
    const int*   eidx   = (const int*)d_in[1];
    const int*   etype  = (const int*)d_in[2];
    const float* basis1 = (const float*)d_in[3];
    const float* att1   = (const float*)d_in[4];
    const float* gw1    = (const float*)d_in[5];
    const float* root1  = (const float*)d_in[6];
    const float* bias1  = (const float*)d_in[7];
    const float* basis2 = (const float*)d_in[8];
    const float* att2   = (const float*)d_in[9];
    const float* gw2    = (const float*)d_in[10];
    const float* root2  = (const float*)d_in[11];
    const float* bias2  = (const float*)d_in[12];
    float* out = (float*)d_out;

    float *wcat1, *wcat2, *ybuf, *hbuf, *gate;
    cudaGetSymbolAddress((void**)&wcat1, d_wcat1);
    cudaGetSymbolAddress((void**)&wcat2, d_wcat2);
    cudaGetSymbolAddress((void**)&ybuf,  d_ybuf);
    cudaGetSymbolAddress((void**)&hbuf,  d_hbuf);
    cudaGetSymbolAddress((void**)&gate,  d_gate);

    const int ZN4 = (NREL * N_NODES * H) / 4;
    dim3 gemm_grid(H / BN, (N_NODES + BM - 1) / BM);

    // Weight assembly (both layers)
    k_wcat<<<(HH + 255) / 256, 256>>>(basis1, att1, root1, wcat1);
    k_wcat<<<(HH + 255) / 256, 256>>>(basis2, att2, root2, wcat2);

    // ----- layer 1 -----
    k_gates<<<(N_NODES * 32 + 255) / 256, 256>>>(x, gw1, gate);
    k_zero<<<(ZN4 + 255) / 256, 256>>>((float4*)ybuf, ZN4);
    k_scatter<<<(N_EDGES * 32 + 255) / 256, 256>>>(x, eidx, etype, gate, ybuf);
    k_gemm<<<gemm_grid, 256>>>(ybuf, x, wcat1, bias1, hbuf, 1);

    // ----- layer 2 -----
    k_gates<<<(N_NODES * 32 + 255) / 256, 256>>>(hbuf, gw2, gate);
    k_zero<<<(ZN4 + 255) / 256, 256>>>((float4*)ybuf, ZN4);
    k_scatter<<<(N_EDGES * 32 + 255) / 256, 256>>>(hbuf, eidx, etype, gate, ybuf);
    k_gemm<<<gemm_grid, 256>>>(ybuf, hbuf, wcat2, bias2, out, 0);
}